// round 2
// baseline (speedup 1.0000x reference)
#include <cuda_runtime.h>
#include <cuda_bf16.h>
#include <mma.h>

using namespace nvcuda;

#define T_ROWS    8192
#define K_DIM     4096
#define N_NODES   63
#define N_PAD     64
#define DEPTH_    6
#define N_LEAVES  64
#define NB_CLS    10

#define MT        64          // rows per block
#define KC        64          // k-chunk
#define LD        72          // smem leading dim (elems), mult of 8 for wmma
#define NTHREADS  256
#define NBLOCKS   (T_ROWS / MT)   // 128

__device__ float g_partial[NBLOCKS];

__global__ void __launch_bounds__(NTHREADS) sdt_main(
    const float* __restrict__ X, const float* __restrict__ W,
    const float* __restrict__ bias, const float* __restrict__ beta,
    const float* __restrict__ leaf_dist, const float* __restrict__ cls_r)
{
    // GEMM smem (double-buffered bf16 X and W tiles); epilogue aliases the
    // X region as an fp32 accumulator tile (after the final barrier).
    __shared__ __align__(16) unsigned char smraw[2 * MT * LD * 2 + 2 * N_PAD * LD * 2];
    __nv_bfloat16 (*Xs)[MT][LD]   = reinterpret_cast<__nv_bfloat16 (*)[MT][LD]>(smraw);
    __nv_bfloat16 (*Ws)[N_PAD][LD] = reinterpret_cast<__nv_bfloat16 (*)[N_PAD][LD]>(smraw + 2 * MT * LD * 2);
    float (*accS)[LD] = reinterpret_cast<float (*)[LD]>(smraw);
    __shared__ float leaf_r[N_LEAVES];
    __shared__ float red_s[8];

    const int tid  = threadIdx.x;
    const int wid  = tid >> 5;
    const int lane = tid & 31;
    const int r0   = tid >> 4;   // 0..15, base row for loads
    const int c4   = tid & 15;   // float4 column within chunk
    const long mrow0 = (long)blockIdx.x * MT;

    // Per-leaf expected reward: softmax(leaf_dist)·class_reward (cheap, per block)
    if (tid < N_LEAVES) {
        const float* ldp = leaf_dist + tid * NB_CLS;
        float mx = ldp[0];
        #pragma unroll
        for (int c = 1; c < NB_CLS; c++) mx = fmaxf(mx, ldp[c]);
        float se = 0.f, sr = 0.f;
        #pragma unroll
        for (int c = 0; c < NB_CLS; c++) {
            float e = __expf(ldp[c] - mx);
            se += e; sr += e * cls_r[c];
        }
        leaf_r[tid] = sr / se;
    }

    float4 xr[4], wr[4];
    auto load_regs = [&](int c) {
        #pragma unroll
        for (int i = 0; i < 4; i++) {
            int row = r0 + 16 * i;
            xr[i] = *reinterpret_cast<const float4*>(&X[(mrow0 + row) * K_DIM + c * KC + c4 * 4]);
            if (row < N_NODES)
                wr[i] = *reinterpret_cast<const float4*>(&W[(long)row * K_DIM + c * KC + c4 * 4]);
            else
                wr[i] = make_float4(0.f, 0.f, 0.f, 0.f);
        }
    };
    auto store_smem = [&](int buf) {
        #pragma unroll
        for (int i = 0; i < 4; i++) {
            int row = r0 + 16 * i;
            __nv_bfloat162* px = reinterpret_cast<__nv_bfloat162*>(&Xs[buf][row][c4 * 4]);
            px[0] = __floats2bfloat162_rn(xr[i].x, xr[i].y);
            px[1] = __floats2bfloat162_rn(xr[i].z, xr[i].w);
            __nv_bfloat162* pw = reinterpret_cast<__nv_bfloat162*>(&Ws[buf][row][c4 * 4]);
            pw[0] = __floats2bfloat162_rn(wr[i].x, wr[i].y);
            pw[1] = __floats2bfloat162_rn(wr[i].z, wr[i].w);
        }
    };

    // 8 warps cover the 64x64 output: 4 m-tiles x 4 n-tiles of 16x16; each warp
    // owns 1 m-tile and 2 n-tiles.
    const int mtile = wid & 3;
    const int nbase = (wid >> 2) * 2;

    wmma::fragment<wmma::accumulator, 16, 16, 16, float> acc0, acc1;
    wmma::fill_fragment(acc0, 0.f);
    wmma::fill_fragment(acc1, 0.f);

    load_regs(0);
    store_smem(0);
    __syncthreads();

    const int NCHUNK = K_DIM / KC;   // 64
    for (int c = 0; c < NCHUNK; c++) {
        int buf = c & 1;
        if (c + 1 < NCHUNK) load_regs(c + 1);   // prefetch next chunk (LDG in flight over MMA)
        #pragma unroll
        for (int ks = 0; ks < KC / 16; ks++) {
            wmma::fragment<wmma::matrix_a, 16, 16, 16, __nv_bfloat16, wmma::row_major> fa;
            wmma::load_matrix_sync(fa, &Xs[buf][mtile * 16][ks * 16], LD);
            wmma::fragment<wmma::matrix_b, 16, 16, 16, __nv_bfloat16, wmma::col_major> fb0, fb1;
            wmma::load_matrix_sync(fb0, &Ws[buf][nbase * 16][ks * 16], LD);
            wmma::load_matrix_sync(fb1, &Ws[buf][(nbase + 1) * 16][ks * 16], LD);
            wmma::mma_sync(acc0, fa, fb0, acc0);
            wmma::mma_sync(acc1, fa, fb1, acc1);
        }
        if (c + 1 < NCHUNK) store_smem((c + 1) & 1);  // other buffer; prev readers done at prior barrier
        __syncthreads();
    }

    // Dump accumulators (aliases X smem; safe after final barrier above)
    wmma::store_matrix_sync(&accS[mtile * 16][nbase * 16],       acc0, LD, wmma::mem_row_major);
    wmma::store_matrix_sync(&accS[mtile * 16][(nbase + 1) * 16], acc1, LD, wmma::mem_row_major);
    __syncthreads();

    // Epilogue: one thread per row, bottom-up tree collapse against leaf_r
    float rowval = 0.f;
    if (tid < MT) {
        float v[N_LEAVES];
        #pragma unroll
        for (int j = 0; j < N_LEAVES; j++) v[j] = leaf_r[j];
        #pragma unroll
        for (int lvl = DEPTH_ - 1; lvl >= 0; lvl--) {
            int base = (1 << lvl) - 1;
            #pragma unroll
            for (int i = 0; i < (1 << lvl); i++) {
                int n = base + i;
                float z = accS[tid][n];
                float a = beta[n] * (z + bias[n]);
                float p = 1.f / (1.f + __expf(-a));
                v[i] = p * v[2 * i] + (1.f - p) * v[2 * i + 1];
            }
        }
        rowval = v[0];
    }

    // Deterministic per-block reduction → per-block partial
    #pragma unroll
    for (int o = 16; o > 0; o >>= 1) rowval += __shfl_down_sync(0xffffffffu, rowval, o);
    if (lane == 0) red_s[wid] = rowval;
    __syncthreads();
    if (tid == 0) {
        float s = 0.f;
        #pragma unroll
        for (int i = 0; i < 8; i++) s += red_s[i];
        g_partial[blockIdx.x] = s;
    }
}

// Fixed-order final reduction (deterministic; also overwrites poisoned d_out)
__global__ void sdt_reduce(float* __restrict__ out) {
    __shared__ float rs[4];
    int tid = threadIdx.x;
    float v = g_partial[tid];
    #pragma unroll
    for (int o = 16; o > 0; o >>= 1) v += __shfl_down_sync(0xffffffffu, v, o);
    if ((tid & 31) == 0) rs[tid >> 5] = v;
    __syncthreads();
    if (tid == 0) out[0] = rs[0] + rs[1] + rs[2] + rs[3];
}

extern "C" void kernel_launch(void* const* d_in, const int* in_sizes, int n_in,
                              void* d_out, int out_size) {
    const float* X         = (const float*)d_in[0];
    const float* W         = (const float*)d_in[1];
    const float* b         = (const float*)d_in[2];
    const float* beta      = (const float*)d_in[3];
    const float* leaf_dist = (const float*)d_in[4];
    const float* cls_r     = (const float*)d_in[5];

    sdt_main<<<NBLOCKS, NTHREADS>>>(X, W, b, beta, leaf_dist, cls_r);
    sdt_reduce<<<1, 128>>>((float*)d_out);
}